// round 4
// baseline (speedup 1.0000x reference)
#include <cuda_runtime.h>
#include <math.h>

#define B_   64
#define T_   1024
#define D_   256
#define H_   1024
#define G4   4096   // 4*H
#define NBLK 128
#define NTHR 256

// ---------------- scratch (static device allocations; no cudaMalloc) ----------------
__device__ float g_xg[(size_t)B_ * T_ * G4];     // 1 GiB, reused by both layers
__device__ float g_y0[(size_t)B_ * T_ * H_];     // 256 MB layer-0 outputs
__device__ float g_WT_ih0[(size_t)D_ * G4];      // [K][4H] transposed weights
__device__ float g_WT_hh0[(size_t)H_ * G4];
__device__ float g_WT_ih1[(size_t)H_ * G4];
__device__ float g_WT_hh1[(size_t)H_ * G4];
__device__ float g_hA[B_ * H_];                  // h ping-pong
__device__ float g_hB[B_ * H_];
__device__ float g_c[B_ * H_];                   // final c only
__device__ unsigned g_bar_cnt;                   // grid barrier (monotonic)
__device__ unsigned g_bar_gen;

// ---------------- weight transpose: W[4H, K] -> WT[K, 4H] ----------------
__global__ void transpose_k(const float* __restrict__ W, int K, int which) {
    float* WT = (which == 0) ? g_WT_ih0 :
                (which == 1) ? g_WT_hh0 :
                (which == 2) ? g_WT_ih1 : g_WT_hh1;
    __shared__ float tile[32][33];
    int c0 = blockIdx.x * 32;   // K dim
    int r0 = blockIdx.y * 32;   // 4H dim
    #pragma unroll
    for (int i = 0; i < 32; i += 8)
        tile[threadIdx.y + i][threadIdx.x] =
            W[(size_t)(r0 + threadIdx.y + i) * K + c0 + threadIdx.x];
    __syncthreads();
    #pragma unroll
    for (int i = 0; i < 32; i += 8)
        WT[(size_t)(c0 + threadIdx.y + i) * G4 + r0 + threadIdx.x] =
            tile[threadIdx.x][threadIdx.y + i];
}

// ---------------- xg GEMM: g_xg[M,4096] = X[M,K] @ WT[K,4096] + b1 + b2 ----------------
// BM=128, BN=64, BK=16, 256 threads, 8x4 microtile, register double-buffered.
__global__ void __launch_bounds__(256)
gemm_xg(const float* __restrict__ Xin, int K, int which,
        const float* __restrict__ b1, const float* __restrict__ b2) {
    const float* __restrict__ X  = (which == 1) ? g_y0 : Xin;
    const float* __restrict__ WT = (which == 1) ? g_WT_ih1 : g_WT_ih0;

    __shared__ float As[2][16 * 132];   // [k][m], padded row 132
    __shared__ float Bs[2][16 * 64];    // [k][n]

    int tid = threadIdx.x;
    size_t m0 = (size_t)blockIdx.y * 128;
    int n0 = blockIdx.x * 64;
    int cx = tid & 15, ry = tid >> 4;
    int c0 = cx * 4, r0 = ry * 8;

    float acc[8][4] = {};
    float4 ra[2], rb;

    // prolog: load chunk 0
    #pragma unroll
    for (int p = 0; p < 2; p++) {
        int idx = tid + p * 256;
        int m = idx >> 2, kq = idx & 3;
        ra[p] = *(const float4*)&X[(m0 + m) * K + kq * 4];
    }
    {
        int n4 = tid & 15, k = tid >> 4;
        rb = *(const float4*)&WT[(size_t)k * G4 + n0 + n4 * 4];
    }
    #pragma unroll
    for (int p = 0; p < 2; p++) {
        int idx = tid + p * 256;
        int m = idx >> 2, kq = idx & 3;
        As[0][(kq * 4 + 0) * 132 + m] = ra[p].x;
        As[0][(kq * 4 + 1) * 132 + m] = ra[p].y;
        As[0][(kq * 4 + 2) * 132 + m] = ra[p].z;
        As[0][(kq * 4 + 3) * 132 + m] = ra[p].w;
    }
    {
        int n4 = tid & 15, k = tid >> 4;
        *(float4*)&Bs[0][k * 64 + n4 * 4] = rb;
    }

    int buf = 0;
    for (int kk = 0; kk < K; kk += 16) {
        __syncthreads();
        bool more = (kk + 16) < K;
        if (more) {
            #pragma unroll
            for (int p = 0; p < 2; p++) {
                int idx = tid + p * 256;
                int m = idx >> 2, kq = idx & 3;
                ra[p] = *(const float4*)&X[(m0 + m) * K + kk + 16 + kq * 4];
            }
            int n4 = tid & 15, k = tid >> 4;
            rb = *(const float4*)&WT[(size_t)(kk + 16 + k) * G4 + n0 + n4 * 4];
        }
        #pragma unroll
        for (int k = 0; k < 16; k++) {
            float4 bv = *(const float4*)&Bs[buf][k * 64 + c0];
            float4 a0 = *(const float4*)&As[buf][k * 132 + r0];
            float4 a1 = *(const float4*)&As[buf][k * 132 + r0 + 4];
            float am[8] = {a0.x, a0.y, a0.z, a0.w, a1.x, a1.y, a1.z, a1.w};
            float bn[4] = {bv.x, bv.y, bv.z, bv.w};
            #pragma unroll
            for (int i = 0; i < 8; i++)
                #pragma unroll
                for (int j = 0; j < 4; j++)
                    acc[i][j] += am[i] * bn[j];
        }
        if (more) {
            #pragma unroll
            for (int p = 0; p < 2; p++) {
                int idx = tid + p * 256;
                int m = idx >> 2, kq = idx & 3;
                As[buf ^ 1][(kq * 4 + 0) * 132 + m] = ra[p].x;
                As[buf ^ 1][(kq * 4 + 1) * 132 + m] = ra[p].y;
                As[buf ^ 1][(kq * 4 + 2) * 132 + m] = ra[p].z;
                As[buf ^ 1][(kq * 4 + 3) * 132 + m] = ra[p].w;
            }
            int n4 = tid & 15, k = tid >> 4;
            *(float4*)&Bs[buf ^ 1][k * 64 + n4 * 4] = rb;
            buf ^= 1;
        }
    }

    float bias[4];
    #pragma unroll
    for (int j = 0; j < 4; j++)
        bias[j] = b1[n0 + c0 + j] + b2[n0 + c0 + j];
    #pragma unroll
    for (int i = 0; i < 8; i++) {
        float4 o;
        o.x = acc[i][0] + bias[0];
        o.y = acc[i][1] + bias[1];
        o.z = acc[i][2] + bias[2];
        o.w = acc[i][3] + bias[3];
        *(float4*)&g_xg[(m0 + r0 + i) * G4 + n0 + c0] = o;
    }
}

// ---------------- zero h (read buffer) and barrier state ----------------
__global__ void zero_state() {
    int i = blockIdx.x * blockDim.x + threadIdx.x;
    if (i < B_ * H_) g_hA[i] = 0.f;
    if (i == 0) { g_bar_cnt = 0u; g_bar_gen = 0u; }
}

// ---------------- grid-wide barrier (all 128 blocks resident) ----------------
__device__ __forceinline__ void grid_sync(unsigned target) {
    __threadfence();
    __syncthreads();
    if (threadIdx.x == 0) {
        unsigned arrived = atomicAdd(&g_bar_cnt, 1u) + 1u;
        if ((arrived & (NBLK - 1)) == 0u) {
            atomicExch(&g_bar_gen, arrived >> 7);   // 128 arrivals per generation
        } else {
            while (*(volatile unsigned*)&g_bar_gen < target) __nanosleep(64);
        }
        __threadfence();
    }
    __syncthreads();
}

// ---------------- persistent LSTM recurrence: all 1024 steps in one kernel ----------------
// 128 blocks x 256 threads. Block owns j0..j0+7 (8 h-cols = 32 gate-cols).
// W_hh slice (32 cols x 1024 K = 128KB) cached in SMEM for the whole kernel.
// Threads split K in two halves (512 each), 4x4 microtile per 128-thread half.
extern __shared__ float smem[];
// layout: Ws [1024*32] | As [2 half][2 buf][32k * 68] | Gs [2 half][32 c][64 b]
#define WS(k, c)          smem[(k) * 32 + (c)]
#define AS(h, bf, k, b)   smem[32768 + ((((h) * 2 + (bf)) * 32 + (k)) * 68) + (b)]
#define GS(h, c, b)       smem[41472 + (((h) * 32 + (c)) * 64) + (b)]
#define SMEM_BYTES        ((32768 + 8704 + 4096) * 4)   // 182272

__global__ void __launch_bounds__(NTHR, 1)
lstm_persist(int layer) {
    const float* __restrict__ WT = layer ? g_WT_hh1 : g_WT_hh0;
    int tid = threadIdx.x;
    int j0 = blockIdx.x * 8;

    // ---- one-time W_hh slice preload: Ws[k][c], c = gate*8 + jj ----
    for (int idx = tid; idx < 32 * H_; idx += NTHR) {
        int c = idx & 31, k = idx >> 5;
        WS(k, c) = WT[(size_t)k * G4 + (c >> 3) * H_ + j0 + (c & 7)];
    }

    int half = tid >> 7;        // K range [half*512, half*512+512)
    int t128 = tid & 127;
    int cx = t128 & 7,  c0 = cx * 4;
    int by = t128 >> 3, b0 = by * 4;
    int kofs = half * 512;

    // cell state in registers: thread owns cells idx = tid + p*256 (p<2)
    float creg[2] = {0.f, 0.f};

    __syncthreads();

    for (int t = 0; t < T_; t++) {
        const float* __restrict__ hsrc = (t & 1) ? g_hB : g_hA;
        float* __restrict__       hdst = (t & 1) ? g_hA : g_hB;

        float acc[4][4] = {};
        float ra[16];

        // prolog: chunk 0 of this half's K range
        #pragma unroll
        for (int p = 0; p < 16; p++) {
            int idx = t128 + p * 128;           // 0..2047: b = idx>>5, k = idx&31
            ra[p] = __ldcg(&hsrc[(idx >> 5) * H_ + kofs + (idx & 31)]);
        }
        #pragma unroll
        for (int p = 0; p < 16; p++) {
            int idx = t128 + p * 128;
            AS(half, 0, idx & 31, idx >> 5) = ra[p];
        }

        int buf = 0;
        for (int kc = 0; kc < 512; kc += 32) {
            __syncthreads();
            bool more = (kc + 32) < 512;
            if (more) {
                #pragma unroll
                for (int p = 0; p < 16; p++) {
                    int idx = t128 + p * 128;
                    ra[p] = __ldcg(&hsrc[(idx >> 5) * H_ + kofs + kc + 32 + (idx & 31)]);
                }
            }
            #pragma unroll
            for (int k = 0; k < 32; k++) {
                float4 wv = *(const float4*)&WS(kofs + kc + k, c0);
                float4 av = *(const float4*)&AS(half, buf, k, b0);
                float am[4] = {av.x, av.y, av.z, av.w};
                float wn[4] = {wv.x, wv.y, wv.z, wv.w};
                #pragma unroll
                for (int bi = 0; bi < 4; bi++)
                    #pragma unroll
                    for (int ci = 0; ci < 4; ci++)
                        acc[bi][ci] += am[bi] * wn[ci];
            }
            if (more) {
                #pragma unroll
                for (int p = 0; p < 16; p++) {
                    int idx = t128 + p * 128;
                    AS(half, buf ^ 1, idx & 31, idx >> 5) = ra[p];
                }
                buf ^= 1;
            }
        }

        // ---- exchange partial gates through SMEM (per-half, summed at read) ----
        #pragma unroll
        for (int ci = 0; ci < 4; ci++)
            #pragma unroll
            for (int bi = 0; bi < 4; bi++)
                GS(half, c0 + ci, b0 + bi) = acc[bi][ci];
        __syncthreads();

        // ---- pointwise gates: 512 cells, 2 per thread (stable ownership => c in regs) ----
        #pragma unroll
        for (int p = 0; p < 2; p++) {
            int idx = tid + p * 256;            // 0..511
            int jj = idx & 7, b = idx >> 3;
            int j = j0 + jj;
            size_t xb = ((size_t)b * T_ + t) * G4 + j;
            float gi = GS(0, 0 * 8 + jj, b) + GS(1, 0 * 8 + jj, b) + g_xg[xb];
            float gf = GS(0, 1 * 8 + jj, b) + GS(1, 1 * 8 + jj, b) + g_xg[xb + H_];
            float gg = GS(0, 2 * 8 + jj, b) + GS(1, 2 * 8 + jj, b) + g_xg[xb + 2 * H_];
            float go = GS(0, 3 * 8 + jj, b) + GS(1, 3 * 8 + jj, b) + g_xg[xb + 3 * H_];
            float iv = 1.f / (1.f + __expf(-gi));
            float fv = 1.f / (1.f + __expf(-gf));
            float gv = tanhf(gg);
            float ov = 1.f / (1.f + __expf(-go));
            float cn = fv * creg[p] + iv * gv;
            creg[p] = cn;
            float hn = ov * tanhf(cn);
            int hc = b * H_ + j;
            hdst[hc] = hn;
            if (layer == 0)
                g_y0[((size_t)b * T_ + t) * H_ + j] = hn;
            if (t == T_ - 1)
                g_c[hc] = cn;
        }

        if (t + 1 < T_)
            grid_sync((unsigned)(t + 1));
    }
}

// ---------------- write final h, c for one layer into d_out ----------------
// out layout: h[2][B][H] then c[2][B][H]. Final h is in g_hA (T=1024 even).
__global__ void copy_out(float* __restrict__ out, int layer) {
    int i = blockIdx.x * blockDim.x + threadIdx.x;
    if (i < B_ * H_) {
        out[(size_t)layer * B_ * H_ + i]       = g_hA[i];
        out[(size_t)(2 + layer) * B_ * H_ + i] = g_c[i];
    }
}

// ---------------- host ----------------
extern "C" void kernel_launch(void* const* d_in, const int* in_sizes, int n_in,
                              void* d_out, int out_size) {
    const float* x     = (const float*)d_in[0];
    const float* W_ih0 = (const float*)d_in[1];
    const float* W_hh0 = (const float*)d_in[2];
    const float* b_ih0 = (const float*)d_in[3];
    const float* b_hh0 = (const float*)d_in[4];
    const float* W_ih1 = (const float*)d_in[5];
    const float* W_hh1 = (const float*)d_in[6];
    const float* b_ih1 = (const float*)d_in[7];
    const float* b_hh1 = (const float*)d_in[8];
    float* out = (float*)d_out;

    cudaFuncSetAttribute(lstm_persist,
                         cudaFuncAttributeMaxDynamicSharedMemorySize, SMEM_BYTES);

    dim3 tb(32, 8);
    transpose_k<<<dim3(D_ / 32, G4 / 32), tb>>>(W_ih0, D_, 0);
    transpose_k<<<dim3(H_ / 32, G4 / 32), tb>>>(W_hh0, H_, 1);
    transpose_k<<<dim3(H_ / 32, G4 / 32), tb>>>(W_ih1, H_, 2);
    transpose_k<<<dim3(H_ / 32, G4 / 32), tb>>>(W_hh1, H_, 3);

    // ---- layer 0 ----
    gemm_xg<<<dim3(G4 / 64, (B_ * T_) / 128), 256>>>(x, D_, 0, b_ih0, b_hh0);
    zero_state<<<256, 256>>>();
    lstm_persist<<<NBLK, NTHR, SMEM_BYTES>>>(0);
    copy_out<<<256, 256>>>(out, 0);

    // ---- layer 1 ----
    gemm_xg<<<dim3(G4 / 64, (B_ * T_) / 128), 256>>>(nullptr, H_, 1, b_ih1, b_hh1);
    zero_state<<<256, 256>>>();
    lstm_persist<<<NBLK, NTHR, SMEM_BYTES>>>(1);
    copy_out<<<256, 256>>>(out, 1);
}